// round 15
// baseline (speedup 1.0000x reference)
#include <cuda_runtime.h>
#include <cuda_bf16.h>
#include <cuda_fp16.h>
#include <cstdint>

#define B_SZ   1024
#define K_SZ   512
#define D_SZ   256
#define H_SZ   8
#define HD_SZ  32
#define EPS_LN 1e-5f
#define Q_SCALE 0.17677669529663687f   // 32^-0.5

// ---------------- scratch (device globals; allocation-free) ----------------
__device__ float  g_q[B_SZ * D_SZ];                       // 1 MB
__device__ __half g_kh[(size_t)B_SZ * K_SZ * D_SZ];       // 256 MB (LN'd k, fp16)
__device__ __half g_vh[(size_t)B_SZ * K_SZ * D_SZ];       // 256 MB (v, fp16)
__device__ __half g_wh[2][D_SZ * D_SZ];                   // W fp16 (0=Wk,1=Wv)

// ======================= helpers ==============================
__device__ __forceinline__ uint32_t smem_u32(const void* p) {
    uint32_t a;
    asm("{ .reg .u64 t; cvta.to.shared.u64 t, %1; cvt.u32.u64 %0, t; }"
        : "=r"(a) : "l"(p));
    return a;
}
__device__ __forceinline__ uint32_t pack_h2(float a, float b) {
    __half2 t = __floats2half2_rn(a, b);
    return *reinterpret_cast<uint32_t*>(&t);
}

#define LDSM4(r0, r1, r2, r3, addr) \
    asm volatile("ldmatrix.sync.aligned.m8n8.x4.shared.b16 {%0,%1,%2,%3}, [%4];" \
                 : "=r"(r0), "=r"(r1), "=r"(r2), "=r"(r3) : "r"(addr))

#define MMA16816H(c, a, b) \
    asm volatile("mma.sync.aligned.m16n8k16.row.col.f32.f16.f16.f32 " \
                 "{%0,%1,%2,%3}, {%4,%5,%6,%7}, {%8,%9}, {%0,%1,%2,%3};" \
                 : "+f"((c)[0]), "+f"((c)[1]), "+f"((c)[2]), "+f"((c)[3]) \
                 : "r"((a)[0]), "r"((a)[1]), "r"((a)[2]), "r"((a)[3]), \
                   "r"((b)[0]), "r"((b)[1]))

#define CP16(dst, gsrc) \
    asm volatile("cp.async.ca.shared.global [%0], [%1], 16;" \
                 :: "r"(dst), "l"(gsrc) : "memory")
#define CP_COMMIT() asm volatile("cp.async.commit_group;" ::: "memory")
#define CP_WAIT0()  asm volatile("cp.async.wait_group 0;" ::: "memory")

// ============================================================================
// Kernel 0: convert Wk/Wv to fp16.  grid=512, block=256
// ============================================================================
__global__ void wsplit_kernel(const float* __restrict__ Wk,
                              const float* __restrict__ Wv)
{
    const int sel = blockIdx.x & 1;
    const int i   = (blockIdx.x >> 1) * 256 + threadIdx.x;
    g_wh[sel][i] = __float2half_rn((sel ? Wv : Wk)[i]);
}

// ============================================================================
// Kernel 1: q = LN_perhead(x_q @ Wq^T) * scale          grid=B, block=256
// ============================================================================
__global__ void qproj_kernel(const float* __restrict__ xq,
                             const float* __restrict__ Wq,
                             const float* __restrict__ qn_w,
                             const float* __restrict__ qn_b)
{
    const int b = blockIdx.x;
    const int j = threadIdx.x;
    const int lane = j & 31;

    __shared__ float xrow[D_SZ];
    xrow[j] = xq[b * D_SZ + j];
    __syncthreads();

    const float4* w4 = reinterpret_cast<const float4*>(Wq + (size_t)j * D_SZ);
    const float4* x4 = reinterpret_cast<const float4*>(xrow);
    float acc = 0.f;
#pragma unroll
    for (int d = 0; d < D_SZ / 4; ++d) {
        float4 w = w4[d];
        float4 x = x4[d];
        acc = fmaf(w.x, x.x, acc);
        acc = fmaf(w.y, x.y, acc);
        acc = fmaf(w.z, x.z, acc);
        acc = fmaf(w.w, x.w, acc);
    }
    float s = acc, ss = acc * acc;
#pragma unroll
    for (int o = 16; o > 0; o >>= 1) {
        s  += __shfl_xor_sync(0xffffffffu, s,  o);
        ss += __shfl_xor_sync(0xffffffffu, ss, o);
    }
    const float mu  = s * (1.f / 32.f);
    const float var = ss * (1.f / 32.f) - mu * mu;
    const float r   = rsqrtf(var + EPS_LN);
    float q = (acc - mu) * r * qn_w[lane] + qn_b[lane];
    g_q[b * D_SZ + j] = q * Q_SCALE;
}

// ============================================================================
// Kernel 2 (mma.sync fp16, W-RESIDENT PERSISTENT): grid=296, block=512.
//   bid < 148  -> K projection (LN),  bid >= 148 -> V projection.
//   Each CTA loads its full W (128 KB) into smem ONCE via cp.async, then
//   loops over M-tiles (128 rows) streaming only X (double-buffered 2x16 KB).
//   Steady-state chunk loop: X LDG+cvt+STS + MMA; no cp.async, no W stores.
//   Warp (mh = wid>>2, hs = wid&3) owns rows [32mh,+32) x cols [64hs,+64).
// ============================================================================
#define CH       64
#define NCH      (D_SZ / CH)      // 4
#define W_OFF    0                 // 4 chunks * (256 rows * 128B) = 128 KB
#define WCHUNK_B 32768
#define X_OFF    131072            // 2 * 16 KB
#define XBUF_B   16384
#define DSM_B    (X_OFF + 2 * XBUF_B + 1024)
#define PT       512
#define M_TILES  ((B_SZ * K_SZ) / 128)   // 4096
#define NSM      148

__global__ void __launch_bounds__(PT, 1)
proj_mma(const float* __restrict__ x_k, const float* __restrict__ x_v,
         const float* __restrict__ lnw, const float* __restrict__ lnb)
{
    extern __shared__ char dsm[];
    char* smp = (char*)((((uintptr_t)dsm) + 1023) & ~(uintptr_t)1023);
    const uint32_t base = smem_u32(smp);

    const int bid  = blockIdx.x;
    const int wsel = (bid >= NSM) ? 1 : 0;         // 0 = K (LN), 1 = V
    const bool do_ln = (wsel == 0);
    const int tile0 = (bid >= NSM) ? (bid - NSM) : bid;
    const float* __restrict__ X = do_ln ? x_k : x_v;
    const __half* __restrict__ Wh = g_wh[wsel];
    __half* __restrict__ Out = do_ln ? g_kh : g_vh;

    const int tid  = threadIdx.x;
    const int wid  = tid >> 5;
    const int lane = tid & 31;
    const int mh   = wid >> 2;       // 0..3 : 32-row stripe
    const int hs   = wid & 3;        // 0..3 : 64-col stripe
    const int g    = lane >> 2;
    const int tg   = lane & 3;

    // ---- load W fully into smem (chunked SW128 layout), once ----
#pragma unroll
    for (int i = 0; i < 16; ++i) {
        const int idx = tid + i * PT;           // 0..8191
        const int row = idx >> 5;               // 0..255
        const int rem = idx & 31;
        const int c   = rem >> 3;               // chunk 0..3
        const int j16 = rem & 7;
        const uint32_t off = (uint32_t)c * WCHUNK_B + (uint32_t)row * 128u +
                             (((uint32_t)j16 * 16u) ^ ((uint32_t)(row & 7) * 16u));
        CP16(base + W_OFF + off,
             (const char*)Wh + (size_t)row * 512 + c * 128 + j16 * 16);
    }
    CP_COMMIT();
    CP_WAIT0();
    __syncthreads();

    // ---- X stage mapping: thread -> row tid>>2, 16 floats of a 64-chunk ----
    const int xrow = tid >> 2;             // 0..127
    const int fgrp = tid & 3;
    const uint32_t xb0   = (uint32_t)fgrp * 32u;
    const uint32_t xswz  = (uint32_t)(xrow & 7) * 16u;
    const uint32_t xoff0 = (uint32_t)xrow * 128u + (xb0 ^ xswz);
    const uint32_t xoff1 = (uint32_t)xrow * 128u + ((xb0 + 16u) ^ xswz);

    // ================= persistent loop over M tiles =================
    for (int tile = tile0; tile < M_TILES; tile += NSM) {
        const size_t m_base = (size_t)tile * 128;
        const float* xptr = X + (m_base + xrow) * D_SZ + fgrp * 16;

        float acc[2][8][4];
#pragma unroll
        for (int i = 0; i < 2; ++i)
#pragma unroll
            for (int j = 0; j < 8; ++j)
#pragma unroll
                for (int cc = 0; cc < 4; ++cc) acc[i][j][cc] = 0.f;

        float4 xr[4];

        auto stage_x = [&](char* ab) {
            const float* xf = reinterpret_cast<const float*>(xr);
            uint4 h0, h1;
            h0.x = pack_h2(xf[0],  xf[1]);  h0.y = pack_h2(xf[2],  xf[3]);
            h0.z = pack_h2(xf[4],  xf[5]);  h0.w = pack_h2(xf[6],  xf[7]);
            h1.x = pack_h2(xf[8],  xf[9]);  h1.y = pack_h2(xf[10], xf[11]);
            h1.z = pack_h2(xf[12], xf[13]); h1.w = pack_h2(xf[14], xf[15]);
            *reinterpret_cast<uint4*>(ab + xoff0) = h0;
            *reinterpret_cast<uint4*>(ab + xoff1) = h1;
        };

        // stage chunk 0
#pragma unroll
        for (int u = 0; u < 4; ++u)
            xr[u] = *reinterpret_cast<const float4*>(xptr + u * 4);
        stage_x(smp + X_OFF);
        __syncthreads();

        // chunk loop
        for (int c = 0; c < NCH; ++c) {
            const int s = c & 1;
            const uint32_t ab = base + X_OFF + (uint32_t)s * XBUF_B;
            const uint32_t wb = base + W_OFF + (uint32_t)c * WCHUNK_B;

            if (c + 1 < NCH) {
                const int kn = (c + 1) * CH;
#pragma unroll
                for (int u = 0; u < 4; ++u)
                    xr[u] = *reinterpret_cast<const float4*>(xptr + kn + u * 4);
            }

#pragma unroll
            for (int ks = 0; ks < 4; ++ks) {
                uint32_t Ah4[2][4], Bh4[8][2];
                {
                    const int ar = lane & 15;
                    const uint32_t akhb = (uint32_t)(lane >> 4) * 16u;
#pragma unroll
                    for (int i = 0; i < 2; ++i) {
                        const int row = 32 * mh + 16 * i + ar;
                        const uint32_t off = (uint32_t)row * 128u +
                            (((uint32_t)ks * 32u + akhb) ^ ((uint32_t)(row & 7) * 16u));
                        LDSM4(Ah4[i][0], Ah4[i][1], Ah4[i][2], Ah4[i][3], ab + off);
                    }
                }
                {
                    const int g2  = lane >> 3;
                    const uint32_t khb = (uint32_t)(g2 & 1) * 16u;
                    const int rsub = ((g2 >> 1) * 8) + (lane & 7);
#pragma unroll
                    for (int p = 0; p < 4; ++p) {
                        const int row = hs * 64 + p * 16 + rsub;
                        const uint32_t off = (uint32_t)row * 128u +
                            (((uint32_t)ks * 32u + khb) ^ ((uint32_t)(row & 7) * 16u));
                        LDSM4(Bh4[2 * p][0], Bh4[2 * p][1], Bh4[2 * p + 1][0], Bh4[2 * p + 1][1],
                              wb + off);
                    }
                }
#pragma unroll
                for (int i = 0; i < 2; ++i)
#pragma unroll
                    for (int j = 0; j < 8; ++j)
                        MMA16816H(acc[i][j], Ah4[i], Bh4[j]);
            }

            if (c + 1 < NCH)
                stage_x(smp + X_OFF + (s ^ 1) * XBUF_B);
            __syncthreads();
        }

        // ================= epilogue: per-head LN + fp16 store =================
        float lw[8][2], lb[8][2];
        if (do_ln) {
#pragma unroll
            for (int j = 0; j < 8; ++j) {
                const int c = (j & 3) * 8 + 2 * tg;   // channel-in-head
                lw[j][0] = lnw[c];     lw[j][1] = lnw[c + 1];
                lb[j][0] = lnb[c];     lb[j][1] = lnb[c + 1];
            }
        }

#pragma unroll
        for (int i = 0; i < 2; ++i) {
#pragma unroll
            for (int half = 0; half < 2; ++half) {
                const int r = 32 * mh + 16 * i + 8 * half + g;
                float v0[8], v1[8];
#pragma unroll
                for (int j = 0; j < 8; ++j) {
                    v0[j] = acc[i][j][2 * half];
                    v1[j] = acc[i][j][2 * half + 1];
                }
                if (do_ln) {
#pragma unroll
                    for (int hd = 0; hd < 2; ++hd) {
                        float s = 0.f, ss = 0.f;
#pragma unroll
                        for (int jj = 0; jj < 4; ++jj) {
                            const int j = hd * 4 + jj;
                            s  += v0[j] + v1[j];
                            ss += v0[j] * v0[j] + v1[j] * v1[j];
                        }
                        s  += __shfl_xor_sync(0xffffffffu, s,  1);
                        ss += __shfl_xor_sync(0xffffffffu, ss, 1);
                        s  += __shfl_xor_sync(0xffffffffu, s,  2);
                        ss += __shfl_xor_sync(0xffffffffu, ss, 2);
                        const float mu  = s * (1.f / 32.f);
                        const float var = ss * (1.f / 32.f) - mu * mu;
                        const float rr  = rsqrtf(var + EPS_LN);
#pragma unroll
                        for (int jj = 0; jj < 4; ++jj) {
                            const int j = hd * 4 + jj;
                            v0[j] = (v0[j] - mu) * rr * lw[j][0] + lb[j][0];
                            v1[j] = (v1[j] - mu) * rr * lw[j][1] + lb[j][1];
                        }
                    }
                }
                __half* orow = Out + (m_base + r) * D_SZ + hs * 64 + 2 * tg;
#pragma unroll
                for (int j = 0; j < 8; ++j)
                    *reinterpret_cast<__half2*>(orow + 8 * j) = __floats2half2_rn(v0[j], v1[j]);
            }
        }
    }
}

// ============================================================================
// Kernel 3: attention over fp16 k/v. grid=B, block=512, 2 CTAs/SM.
//   (unchanged — measured 153us, DRAM 44.5%)
// ============================================================================
__global__ void __launch_bounds__(512, 2)
attn_kernel(const float* __restrict__ Wp,
            const float* __restrict__ n_w,
            const float* __restrict__ n_b,
            float* __restrict__ out)
{
    const int b    = blockIdx.x;
    const int tid  = threadIdx.x;
    const int w    = tid >> 5;
    const int lane = tid & 31;
    const int h    = w & 7;
    const int khalf = w >> 3;      // 0/1 : K rows [0,256) or [256,512)
    const int rg   = lane >> 2;    // row within 8-row group
    const int cs   = lane & 3;     // 8-channel slice

    float qv[8];
    {
        const float4* qp = reinterpret_cast<const float4*>(
            g_q + b * D_SZ + h * HD_SZ + cs * 8);
        float4 a = qp[0], c = qp[1];
        qv[0] = a.x; qv[1] = a.y; qv[2] = a.z; qv[3] = a.w;
        qv[4] = c.x; qv[5] = c.y; qv[6] = c.z; qv[7] = c.w;
    }

    const __half* kbase = g_kh + (size_t)b * K_SZ * D_SZ + (size_t)khalf * 256 * D_SZ
                               + h * HD_SZ + cs * 8;
    const __half* vbase = g_vh + (size_t)b * K_SZ * D_SZ + (size_t)khalf * 256 * D_SZ
                               + h * HD_SZ + cs * 8;

    float m = -1e30f, l = 0.f;
    float acc[8];
#pragma unroll
    for (int e = 0; e < 8; ++e) acc[e] = 0.f;

    uint4 ka, va, kb, vb;

#define ALOAD(i, K, V) do {                                                    \
    const size_t roff = (size_t)((i) * 8 + rg) * D_SZ;                         \
    K = *reinterpret_cast<const uint4*>(kbase + roff);                         \
    V = *reinterpret_cast<const uint4*>(vbase + roff);                         \
} while (0)

#define ADOT(K, sres) do {                                                     \
    const __half2* kh = reinterpret_cast<const __half2*>(&K);                  \
    float s = 0.f;                                                             \
    _Pragma("unroll")                                                          \
    for (int e = 0; e < 4; ++e) {                                              \
        const float2 kf = __half22float2(kh[e]);                               \
        s = fmaf(qv[2 * e], kf.x, s);                                          \
        s = fmaf(qv[2 * e + 1], kf.y, s);                                      \
    }                                                                          \
    s += __shfl_xor_sync(0xffffffffu, s, 1);                                   \
    s += __shfl_xor_sync(0xffffffffu, s, 2);                                   \
    sres = s;                                                                  \
} while (0)

    ALOAD(0, ka, va);
#pragma unroll 1
    for (int it = 0; it < 32; it += 2) {
        ALOAD(it + 1, kb, vb);
        float s0, s1;
        ADOT(ka, s0);
        ADOT(kb, s1);

        const float mn   = fmaxf(m, fmaxf(s0, s1));
        const float corr = __expf(m - mn);
        const float p0   = __expf(s0 - mn);
        const float p1   = __expf(s1 - mn);
        l = l * corr + p0 + p1;
        const __half2* v0h = reinterpret_cast<const __half2*>(&va);
        const __half2* v1h = reinterpret_cast<const __half2*>(&vb);
#pragma unroll
        for (int e = 0; e < 4; ++e) {
            const float2 vf0 = __half22float2(v0h[e]);
            const float2 vf1 = __half22float2(v1h[e]);
            acc[2 * e]     = fmaf(acc[2 * e],     corr, p0 * vf0.x + p1 * vf1.x);
            acc[2 * e + 1] = fmaf(acc[2 * e + 1], corr, p0 * vf0.y + p1 * vf1.y);
        }
        m = mn;
        if (it + 2 < 32) ALOAD(it + 2, ka, va);
    }
#undef ALOAD
#undef ADOT

    // ---- intra-warp merge over 8 row-groups (lanes xor 4,8,16) ----
#pragma unroll
    for (int off = 4; off <= 16; off <<= 1) {
        const float pm = __shfl_xor_sync(0xffffffffu, m, off);
        const float pl = __shfl_xor_sync(0xffffffffu, l, off);
        const float MM = fmaxf(m, pm);
        const float ca = __expf(m - MM);
        const float cb = __expf(pm - MM);
        l = l * ca + pl * cb;
#pragma unroll
        for (int e = 0; e < 8; ++e) {
            const float pa = __shfl_xor_sync(0xffffffffu, acc[e], off);
            acc[e] = acc[e] * ca + pa * cb;
        }
        m = MM;
    }

    // ---- cross-warp merge (w and w+8 share a head) ----
    __shared__ float sm[16], sl[16];
    __shared__ float sacc[16][33];
    if (lane == 0) { sm[w] = m; sl[w] = l; }
    if (rg == 0) {
#pragma unroll
        for (int e = 0; e < 8; ++e) sacc[w][cs * 8 + e] = acc[e];
    }
    __syncthreads();

    float o_val = 0.f;
    if (tid < 256) {
        const int hh = tid >> 5;       // head
        const int ch = tid & 31;       // channel within head
        const float m0 = sm[hh], m1 = sm[hh + 8];
        const float M  = fmaxf(m0, m1);
        const float c0 = __expf(m0 - M), c1 = __expf(m1 - M);
        const float L  = sl[hh] * c0 + sl[hh + 8] * c1;
        o_val = (sacc[hh][ch] * c0 + sacc[hh + 8][ch] * c1) / L;
    }

    // ---- block LN over 256 channels (threads 0..255 hold o_val) ----
    __shared__ float sred[2][8];
    if (tid < 256) {
        float s = o_val, ss = o_val * o_val;
#pragma unroll
        for (int off = 16; off > 0; off >>= 1) {
            s  += __shfl_xor_sync(0xffffffffu, s,  off);
            ss += __shfl_xor_sync(0xffffffffu, ss, off);
        }
        if (lane == 0) { sred[0][w] = s; sred[1][w] = ss; }
    }
    __syncthreads();
    float ts = 0.f, tss = 0.f;
#pragma unroll
    for (int i = 0; i < 8; ++i) { ts += sred[0][i]; tss += sred[1][i]; }
    const float mu  = ts * (1.f / 256.f);
    const float var = tss * (1.f / 256.f) - mu * mu;
    const float rln = rsqrtf(var + EPS_LN);

    __shared__ float sn[D_SZ];
    if (tid < 256)
        sn[tid] = (o_val - mu) * rln * n_w[tid] + n_b[tid];
    __syncthreads();

    // ---- out @ Wp^T : 2 threads per output column (split K 128+128) ----
    const int c   = tid & 255;
    const int seg = tid >> 8;
    const float4* w4 = reinterpret_cast<const float4*>(Wp + (size_t)c * D_SZ + seg * 128);
    const float4* x4 = reinterpret_cast<const float4*>(sn + seg * 128);
    float a = 0.f;
#pragma unroll
    for (int d = 0; d < 32; ++d) {
        float4 wv = w4[d];
        float4 xv = x4[d];
        a = fmaf(wv.x, xv.x, a);
        a = fmaf(wv.y, xv.y, a);
        a = fmaf(wv.z, xv.z, a);
        a = fmaf(wv.w, xv.w, a);
    }
    __shared__ float part[256];
    if (seg == 1) part[c] = a;
    __syncthreads();
    if (seg == 0) out[b * D_SZ + c] = a + part[c];
}

// ============================================================================
extern "C" void kernel_launch(void* const* d_in, const int* in_sizes, int n_in,
                              void* d_out, int out_size)
{
    const float* x_q  = (const float*)d_in[0];
    const float* x_k  = (const float*)d_in[1];
    const float* x_v  = (const float*)d_in[2];
    const float* Wq   = (const float*)d_in[3];
    const float* Wk   = (const float*)d_in[4];
    const float* Wv   = (const float*)d_in[5];
    const float* Wp   = (const float*)d_in[6];
    const float* qn_w = (const float*)d_in[7];
    const float* qn_b = (const float*)d_in[8];
    const float* kn_w = (const float*)d_in[9];
    const float* kn_b = (const float*)d_in[10];
    const float* n_w  = (const float*)d_in[11];
    const float* n_b  = (const float*)d_in[12];
    float* out = (float*)d_out;

    cudaFuncSetAttribute(proj_mma,
                         cudaFuncAttributeMaxDynamicSharedMemorySize, DSM_B);

    wsplit_kernel<<<512, 256>>>(Wk, Wv);
    qproj_kernel<<<B_SZ, 256>>>(x_q, Wq, qn_w, qn_b);
    proj_mma<<<2 * NSM, PT, DSM_B>>>(x_k, x_v, kn_w, kn_b);
    attn_kernel<<<B_SZ, 512>>>(Wp, n_w, n_b, out);
}

// round 16
// speedup vs baseline: 1.1301x; 1.1301x over previous
#include <cuda_runtime.h>
#include <cuda_bf16.h>
#include <cuda_fp16.h>
#include <cstdint>

#define B_SZ   1024
#define K_SZ   512
#define D_SZ   256
#define H_SZ   8
#define HD_SZ  32
#define EPS_LN 1e-5f
#define Q_SCALE 0.17677669529663687f   // 32^-0.5

// ---------------- scratch (device globals; allocation-free) ----------------
__device__ float  g_q[B_SZ * D_SZ];                       // 1 MB
__device__ __half g_kh[(size_t)B_SZ * K_SZ * D_SZ];       // 256 MB (LN'd k, fp16)
__device__ __half g_vh[(size_t)B_SZ * K_SZ * D_SZ];       // 256 MB (v, fp16)
__device__ __half g_wh[2][D_SZ * D_SZ];                   // W fp16 (0=Wk,1=Wv)

// ======================= helpers ==============================
__device__ __forceinline__ uint32_t smem_u32(const void* p) {
    uint32_t a;
    asm("{ .reg .u64 t; cvta.to.shared.u64 t, %1; cvt.u32.u64 %0, t; }"
        : "=r"(a) : "l"(p));
    return a;
}
__device__ __forceinline__ uint32_t pack_h2(float a, float b) {
    __half2 t = __floats2half2_rn(a, b);
    return *reinterpret_cast<uint32_t*>(&t);
}

#define LDSM4(r0, r1, r2, r3, addr) \
    asm volatile("ldmatrix.sync.aligned.m8n8.x4.shared.b16 {%0,%1,%2,%3}, [%4];" \
                 : "=r"(r0), "=r"(r1), "=r"(r2), "=r"(r3) : "r"(addr))

#define MMA16816H(c, a, b) \
    asm volatile("mma.sync.aligned.m16n8k16.row.col.f32.f16.f16.f32 " \
                 "{%0,%1,%2,%3}, {%4,%5,%6,%7}, {%8,%9}, {%0,%1,%2,%3};" \
                 : "+f"((c)[0]), "+f"((c)[1]), "+f"((c)[2]), "+f"((c)[3]) \
                 : "r"((a)[0]), "r"((a)[1]), "r"((a)[2]), "r"((a)[3]), \
                   "r"((b)[0]), "r"((b)[1]))

#define CP16(dst, gsrc) \
    asm volatile("cp.async.ca.shared.global [%0], [%1], 16;" \
                 :: "r"(dst), "l"(gsrc) : "memory")
#define CP_COMMIT() asm volatile("cp.async.commit_group;" ::: "memory")
#define CP_WAIT0()  asm volatile("cp.async.wait_group 0;" ::: "memory")

#define GROUP_BAR(id) \
    asm volatile("bar.sync %0, %1;" :: "r"(id), "r"(128) : "memory")

// ============================================================================
// Kernel 0: convert Wk/Wv to fp16.  grid=512, block=256
// ============================================================================
__global__ void wsplit_kernel(const float* __restrict__ Wk,
                              const float* __restrict__ Wv)
{
    const int sel = blockIdx.x & 1;
    const int i   = (blockIdx.x >> 1) * 256 + threadIdx.x;
    g_wh[sel][i] = __float2half_rn((sel ? Wv : Wk)[i]);
}

// ============================================================================
// Kernel 1: q = LN_perhead(x_q @ Wq^T) * scale          grid=B, block=256
// ============================================================================
__global__ void qproj_kernel(const float* __restrict__ xq,
                             const float* __restrict__ Wq,
                             const float* __restrict__ qn_w,
                             const float* __restrict__ qn_b)
{
    const int b = blockIdx.x;
    const int j = threadIdx.x;
    const int lane = j & 31;

    __shared__ float xrow[D_SZ];
    xrow[j] = xq[b * D_SZ + j];
    __syncthreads();

    const float4* w4 = reinterpret_cast<const float4*>(Wq + (size_t)j * D_SZ);
    const float4* x4 = reinterpret_cast<const float4*>(xrow);
    float acc = 0.f;
#pragma unroll
    for (int d = 0; d < D_SZ / 4; ++d) {
        float4 w = w4[d];
        float4 x = x4[d];
        acc = fmaf(w.x, x.x, acc);
        acc = fmaf(w.y, x.y, acc);
        acc = fmaf(w.z, x.z, acc);
        acc = fmaf(w.w, x.w, acc);
    }
    float s = acc, ss = acc * acc;
#pragma unroll
    for (int o = 16; o > 0; o >>= 1) {
        s  += __shfl_xor_sync(0xffffffffu, s,  o);
        ss += __shfl_xor_sync(0xffffffffu, ss, o);
    }
    const float mu  = s * (1.f / 32.f);
    const float var = ss * (1.f / 32.f) - mu * mu;
    const float r   = rsqrtf(var + EPS_LN);
    float q = (acc - mu) * r * qn_w[lane] + qn_b[lane];
    g_q[b * D_SZ + j] = q * Q_SCALE;
}

// ============================================================================
// Kernel 2 (mma.sync fp16, W-resident persistent, GROUP-DECOUPLED):
//   grid=296, block=512. bid<148 -> K proj (LN), else V proj.
//   W (128 KB) loaded to smem once (whole CTA, single __syncthreads).
//   Then the CTA splits into 4 independent groups (mh = wid>>2, 128 threads,
//   one warp per SMSP). Each group owns a 32-row A slice + its own 2x4 KB
//   double buffer and synchronizes ONLY via named barrier (1+mh, 128).
//   Cross-tile pipelining: chunk0 of the next tile staged during chunk3.
//   Warp (mh, hs=wid&3) computes rows [32mh,+32) x cols [64hs,+64).
// ============================================================================
#define CH       64
#define NCH      (D_SZ / CH)      // 4
#define W_OFF    0                 // 4 chunks * 32 KB = 128 KB
#define WCHUNK_B 32768
#define X_OFF    131072            // 4 groups * 2 * 4 KB = 32 KB
#define GBUF_B   4096
#define DSM_B    (X_OFF + 8 * GBUF_B + 1024)
#define PT       512
#define M_TILES  ((B_SZ * K_SZ) / 128)   // 4096
#define NSM      148

__global__ void __launch_bounds__(PT, 1)
proj_mma(const float* __restrict__ x_k, const float* __restrict__ x_v,
         const float* __restrict__ lnw, const float* __restrict__ lnb)
{
    extern __shared__ char dsm[];
    char* smp = (char*)((((uintptr_t)dsm) + 1023) & ~(uintptr_t)1023);
    const uint32_t base = smem_u32(smp);

    const int bid  = blockIdx.x;
    const int wsel = (bid >= NSM) ? 1 : 0;         // 0 = K (LN), 1 = V
    const bool do_ln = (wsel == 0);
    const int tile0 = (bid >= NSM) ? (bid - NSM) : bid;
    const float* __restrict__ X = do_ln ? x_k : x_v;
    const __half* __restrict__ Wh = g_wh[wsel];
    __half* __restrict__ Out = do_ln ? g_kh : g_vh;

    const int tid  = threadIdx.x;
    const int wid  = tid >> 5;
    const int lane = tid & 31;
    const int mh   = wid >> 2;       // 0..3 : group / 32-row stripe
    const int hs   = wid & 3;        // 0..3 : 64-col stripe
    const int g    = lane >> 2;
    const int tg   = lane & 3;
    const int barid = 1 + mh;

    // ---- load W fully into smem (chunked SW128 layout), once ----
#pragma unroll
    for (int i = 0; i < 16; ++i) {
        const int idx = tid + i * PT;           // 0..8191
        const int row = idx >> 5;               // 0..255
        const int rem = idx & 31;
        const int c   = rem >> 3;               // chunk 0..3
        const int j16 = rem & 7;
        const uint32_t off = (uint32_t)c * WCHUNK_B + (uint32_t)row * 128u +
                             (((uint32_t)j16 * 16u) ^ ((uint32_t)(row & 7) * 16u));
        CP16(base + W_OFF + off,
             (const char*)Wh + (size_t)row * 512 + c * 128 + j16 * 16);
    }
    CP_COMMIT();
    CP_WAIT0();
    __syncthreads();        // only whole-CTA sync in the kernel

    // ---- group-local X stage mapping ----
    const int gtid = tid & 127;            // 0..127 within group
    const int grow = gtid >> 2;            // 0..31 : row within group slice
    const int fgrp = gtid & 3;             // 16-float slice of a 64-chunk
    const uint32_t gbase = base + X_OFF + (uint32_t)mh * (2 * GBUF_B);
    const uint32_t xb0   = (uint32_t)fgrp * 32u;
    const uint32_t xswz  = (uint32_t)(grow & 7) * 16u;
    const uint32_t xoff0 = (uint32_t)grow * 128u + (xb0 ^ xswz);
    const uint32_t xoff1 = (uint32_t)grow * 128u + ((xb0 + 16u) ^ xswz);

    float4 xr[4];
    auto stage_x = [&](uint32_t ab) {
        const float* xf = reinterpret_cast<const float*>(xr);
        uint4 h0, h1;
        h0.x = pack_h2(xf[0],  xf[1]);  h0.y = pack_h2(xf[2],  xf[3]);
        h0.z = pack_h2(xf[4],  xf[5]);  h0.w = pack_h2(xf[6],  xf[7]);
        h1.x = pack_h2(xf[8],  xf[9]);  h1.y = pack_h2(xf[10], xf[11]);
        h1.z = pack_h2(xf[12], xf[13]); h1.w = pack_h2(xf[14], xf[15]);
        *reinterpret_cast<uint4*>(smp + (ab - base) + xoff0) = h0;
        *reinterpret_cast<uint4*>(smp + (ab - base) + xoff1) = h1;
    };

    // per-thread global X pointer for the CURRENT tile (row = 32mh + grow)
    const size_t xrow_off = (size_t)(32 * mh + grow) * D_SZ + fgrp * 16;

    // ---- prologue: stage chunk0 of tile0 into group buf0 ----
    {
        const float* xp = X + (size_t)tile0 * 128 * D_SZ + xrow_off;
#pragma unroll
        for (int u = 0; u < 4; ++u)
            xr[u] = *reinterpret_cast<const float4*>(xp + u * 4);
        stage_x(gbase);
    }
    GROUP_BAR(barid);

    // ================= persistent loop over M tiles =================
    for (int tile = tile0; tile < M_TILES; tile += NSM) {
        const size_t m_base = (size_t)tile * 128;
        const float* xptr = X + m_base * D_SZ + xrow_off;

        float acc[2][8][4];
#pragma unroll
        for (int i = 0; i < 2; ++i)
#pragma unroll
            for (int j = 0; j < 8; ++j)
#pragma unroll
                for (int cc = 0; cc < 4; ++cc) acc[i][j][cc] = 0.f;

#pragma unroll
        for (int c = 0; c < NCH; ++c) {
            const int s = c & 1;
            const uint32_t ab = gbase + (uint32_t)s * GBUF_B;
            const uint32_t wb = base + W_OFF + (uint32_t)c * WCHUNK_B;

            // prefetch: next chunk, or chunk0 of the next tile
            const bool have_next = (c + 1 < NCH) || (tile + NSM < M_TILES);
            if (have_next) {
                const float* np = (c + 1 < NCH)
                    ? (xptr + (c + 1) * CH)
                    : (xptr + (size_t)NSM * 128 * D_SZ);
#pragma unroll
                for (int u = 0; u < 4; ++u)
                    xr[u] = *reinterpret_cast<const float4*>(np + u * 4);
            }

            // ---------------- compute chunk c ----------------
#pragma unroll
            for (int ks = 0; ks < 4; ++ks) {
                uint32_t Ah4[2][4], Bh4[8][2];
                {
                    const int ar = lane & 15;
                    const uint32_t akhb = (uint32_t)(lane >> 4) * 16u;
#pragma unroll
                    for (int i = 0; i < 2; ++i) {
                        const int row = 16 * i + ar;      // within group slice
                        const uint32_t off = (uint32_t)row * 128u +
                            (((uint32_t)ks * 32u + akhb) ^ ((uint32_t)(row & 7) * 16u));
                        LDSM4(Ah4[i][0], Ah4[i][1], Ah4[i][2], Ah4[i][3], ab + off);
                    }
                }
                {
                    const int g2  = lane >> 3;
                    const uint32_t khb = (uint32_t)(g2 & 1) * 16u;
                    const int rsub = ((g2 >> 1) * 8) + (lane & 7);
#pragma unroll
                    for (int p = 0; p < 4; ++p) {
                        const int row = hs * 64 + p * 16 + rsub;
                        const uint32_t off = (uint32_t)row * 128u +
                            (((uint32_t)ks * 32u + khb) ^ ((uint32_t)(row & 7) * 16u));
                        LDSM4(Bh4[2 * p][0], Bh4[2 * p][1], Bh4[2 * p + 1][0], Bh4[2 * p + 1][1],
                              wb + off);
                    }
                }
#pragma unroll
                for (int i = 0; i < 2; ++i)
#pragma unroll
                    for (int j = 0; j < 8; ++j)
                        MMA16816H(acc[i][j], Ah4[i], Bh4[j]);
            }

            // stage prefetched data into the other buffer (c=3 -> buf0 of next tile)
            if (have_next)
                stage_x(gbase + (uint32_t)(s ^ 1) * GBUF_B);
            GROUP_BAR(barid);
        }

        // ================= epilogue: per-head LN + fp16 store =================
        float lw[8][2], lb[8][2];
        if (do_ln) {
#pragma unroll
            for (int j = 0; j < 8; ++j) {
                const int c = (j & 3) * 8 + 2 * tg;   // channel-in-head
                lw[j][0] = lnw[c];     lw[j][1] = lnw[c + 1];
                lb[j][0] = lnb[c];     lb[j][1] = lnb[c + 1];
            }
        }

#pragma unroll
        for (int i = 0; i < 2; ++i) {
#pragma unroll
            for (int half = 0; half < 2; ++half) {
                const int r = 32 * mh + 16 * i + 8 * half + g;
                float v0[8], v1[8];
#pragma unroll
                for (int j = 0; j < 8; ++j) {
                    v0[j] = acc[i][j][2 * half];
                    v1[j] = acc[i][j][2 * half + 1];
                }
                if (do_ln) {
#pragma unroll
                    for (int hd = 0; hd < 2; ++hd) {
                        float s = 0.f, ss = 0.f;
#pragma unroll
                        for (int jj = 0; jj < 4; ++jj) {
                            const int j = hd * 4 + jj;
                            s  += v0[j] + v1[j];
                            ss += v0[j] * v0[j] + v1[j] * v1[j];
                        }
                        s  += __shfl_xor_sync(0xffffffffu, s,  1);
                        ss += __shfl_xor_sync(0xffffffffu, ss, 1);
                        s  += __shfl_xor_sync(0xffffffffu, s,  2);
                        ss += __shfl_xor_sync(0xffffffffu, ss, 2);
                        const float mu  = s * (1.f / 32.f);
                        const float var = ss * (1.f / 32.f) - mu * mu;
                        const float rr  = rsqrtf(var + EPS_LN);
#pragma unroll
                        for (int jj = 0; jj < 4; ++jj) {
                            const int j = hd * 4 + jj;
                            v0[j] = (v0[j] - mu) * rr * lw[j][0] + lb[j][0];
                            v1[j] = (v1[j] - mu) * rr * lw[j][1] + lb[j][1];
                        }
                    }
                }
                __half* orow = Out + (m_base + r) * D_SZ + hs * 64 + 2 * tg;
#pragma unroll
                for (int j = 0; j < 8; ++j)
                    *reinterpret_cast<__half2*>(orow + 8 * j) = __floats2half2_rn(v0[j], v1[j]);
            }
        }
    }
}

// ============================================================================
// Kernel 3: attention over fp16 k/v. grid=B, block=512, 2 CTAs/SM.
//   (unchanged — measured ~153us, DRAM ~44.5%)
// ============================================================================
__global__ void __launch_bounds__(512, 2)
attn_kernel(const float* __restrict__ Wp,
            const float* __restrict__ n_w,
            const float* __restrict__ n_b,
            float* __restrict__ out)
{
    const int b    = blockIdx.x;
    const int tid  = threadIdx.x;
    const int w    = tid >> 5;
    const int lane = tid & 31;
    const int h    = w & 7;
    const int khalf = w >> 3;      // 0/1 : K rows [0,256) or [256,512)
    const int rg   = lane >> 2;    // row within 8-row group
    const int cs   = lane & 3;     // 8-channel slice

    float qv[8];
    {
        const float4* qp = reinterpret_cast<const float4*>(
            g_q + b * D_SZ + h * HD_SZ + cs * 8);
        float4 a = qp[0], c = qp[1];
        qv[0] = a.x; qv[1] = a.y; qv[2] = a.z; qv[3] = a.w;
        qv[4] = c.x; qv[5] = c.y; qv[6] = c.z; qv[7] = c.w;
    }

    const __half* kbase = g_kh + (size_t)b * K_SZ * D_SZ + (size_t)khalf * 256 * D_SZ
                               + h * HD_SZ + cs * 8;
    const __half* vbase = g_vh + (size_t)b * K_SZ * D_SZ + (size_t)khalf * 256 * D_SZ
                               + h * HD_SZ + cs * 8;

    float m = -1e30f, l = 0.f;
    float acc[8];
#pragma unroll
    for (int e = 0; e < 8; ++e) acc[e] = 0.f;

    uint4 ka, va, kb, vb;

#define ALOAD(i, K, V) do {                                                    \
    const size_t roff = (size_t)((i) * 8 + rg) * D_SZ;                         \
    K = *reinterpret_cast<const uint4*>(kbase + roff);                         \
    V = *reinterpret_cast<const uint4*>(vbase + roff);                         \
} while (0)

#define ADOT(K, sres) do {                                                     \
    const __half2* kh = reinterpret_cast<const __half2*>(&K);                  \
    float s = 0.f;                                                             \
    _Pragma("unroll")                                                          \
    for (int e = 0; e < 4; ++e) {                                              \
        const float2 kf = __half22float2(kh[e]);                               \
        s = fmaf(qv[2 * e], kf.x, s);                                          \
        s = fmaf(qv[2 * e + 1], kf.y, s);                                      \
    }                                                                          \
    s += __shfl_xor_sync(0xffffffffu, s, 1);                                   \
    s += __shfl_xor_sync(0xffffffffu, s, 2);                                   \
    sres = s;                                                                  \
} while (0)

    ALOAD(0, ka, va);
#pragma unroll 1
    for (int it = 0; it < 32; it += 2) {
        ALOAD(it + 1, kb, vb);
        float s0, s1;
        ADOT(ka, s0);
        ADOT(kb, s1);

        const float mn   = fmaxf(m, fmaxf(s0, s1));
        const float corr = __expf(m - mn);
        const float p0   = __expf(s0 - mn);
        const float p1   = __expf(s1 - mn);
        l = l * corr + p0 + p1;
        const __half2* v0h = reinterpret_cast<const __half2*>(&va);
        const __half2* v1h = reinterpret_cast<const __half2*>(&vb);
#pragma unroll
        for (int e = 0; e < 4; ++e) {
            const float2 vf0 = __half22float2(v0h[e]);
            const float2 vf1 = __half22float2(v1h[e]);
            acc[2 * e]     = fmaf(acc[2 * e],     corr, p0 * vf0.x + p1 * vf1.x);
            acc[2 * e + 1] = fmaf(acc[2 * e + 1], corr, p0 * vf0.y + p1 * vf1.y);
        }
        m = mn;
        if (it + 2 < 32) ALOAD(it + 2, ka, va);
    }
#undef ALOAD
#undef ADOT

    // ---- intra-warp merge over 8 row-groups (lanes xor 4,8,16) ----
#pragma unroll
    for (int off = 4; off <= 16; off <<= 1) {
        const float pm = __shfl_xor_sync(0xffffffffu, m, off);
        const float pl = __shfl_xor_sync(0xffffffffu, l, off);
        const float MM = fmaxf(m, pm);
        const float ca = __expf(m - MM);
        const float cb = __expf(pm - MM);
        l = l * ca + pl * cb;
#pragma unroll
        for (int e = 0; e < 8; ++e) {
            const float pa = __shfl_xor_sync(0xffffffffu, acc[e], off);
            acc[e] = acc[e] * ca + pa * cb;
        }
        m = MM;
    }

    // ---- cross-warp merge (w and w+8 share a head) ----
    __shared__ float sm[16], sl[16];
    __shared__ float sacc[16][33];
    if (lane == 0) { sm[w] = m; sl[w] = l; }
    if (rg == 0) {
#pragma unroll
        for (int e = 0; e < 8; ++e) sacc[w][cs * 8 + e] = acc[e];
    }
    __syncthreads();

    float o_val = 0.f;
    if (tid < 256) {
        const int hh = tid >> 5;       // head
        const int ch = tid & 31;       // channel within head
        const float m0 = sm[hh], m1 = sm[hh + 8];
        const float M  = fmaxf(m0, m1);
        const float c0 = __expf(m0 - M), c1 = __expf(m1 - M);
        const float L  = sl[hh] * c0 + sl[hh + 8] * c1;
        o_val = (sacc[hh][ch] * c0 + sacc[hh + 8][ch] * c1) / L;
    }

    // ---- block LN over 256 channels (threads 0..255 hold o_val) ----
    __shared__ float sred[2][8];
    if (tid < 256) {
        float s = o_val, ss = o_val * o_val;
#pragma unroll
        for (int off = 16; off > 0; off >>= 1) {
            s  += __shfl_xor_sync(0xffffffffu, s,  off);
            ss += __shfl_xor_sync(0xffffffffu, ss, off);
        }
        if (lane == 0) { sred[0][w] = s; sred[1][w] = ss; }
    }
    __syncthreads();
    float ts = 0.f, tss = 0.f;
#pragma unroll
    for (int i = 0; i < 8; ++i) { ts += sred[0][i]; tss += sred[1][i]; }
    const float mu  = ts * (1.f / 256.f);
    const float var = tss * (1.f / 256.f) - mu * mu;
    const float rln = rsqrtf(var + EPS_LN);

    __shared__ float sn[D_SZ];
    if (tid < 256)
        sn[tid] = (o_val - mu) * rln * n_w[tid] + n_b[tid];
    __syncthreads();

    // ---- out @ Wp^T : 2 threads per output column (split K 128+128) ----
    const int c   = tid & 255;
    const int seg = tid >> 8;
    const float4* w4 = reinterpret_cast<const float4*>(Wp + (size_t)c * D_SZ + seg * 128);
    const float4* x4 = reinterpret_cast<const float4*>(sn + seg * 128);
    float a = 0.f;
#pragma unroll
    for (int d = 0; d < 32; ++d) {
        float4 wv = w4[d];
        float4 xv = x4[d];
        a = fmaf(wv.x, xv.x, a);
        a = fmaf(wv.y, xv.y, a);
        a = fmaf(wv.z, xv.z, a);
        a = fmaf(wv.w, xv.w, a);
    }
    __shared__ float part[256];
    if (seg == 1) part[c] = a;
    __syncthreads();
    if (seg == 0) out[b * D_SZ + c] = a + part[c];
}

// ============================================================================
extern "C" void kernel_launch(void* const* d_in, const int* in_sizes, int n_in,
                              void* d_out, int out_size)
{
    const float* x_q  = (const float*)d_in[0];
    const float* x_k  = (const float*)d_in[1];
    const float* x_v  = (const float*)d_in[2];
    const float* Wq   = (const float*)d_in[3];
    const float* Wk   = (const float*)d_in[4];
    const float* Wv   = (const float*)d_in[5];
    const float* Wp   = (const float*)d_in[6];
    const float* qn_w = (const float*)d_in[7];
    const float* qn_b = (const float*)d_in[8];
    const float* kn_w = (const float*)d_in[9];
    const float* kn_b = (const float*)d_in[10];
    const float* n_w  = (const float*)d_in[11];
    const float* n_b  = (const float*)d_in[12];
    float* out = (float*)d_out;

    cudaFuncSetAttribute(proj_mma,
                         cudaFuncAttributeMaxDynamicSharedMemorySize, DSM_B);

    wsplit_kernel<<<512, 256>>>(Wk, Wv);
    qproj_kernel<<<B_SZ, 256>>>(x_q, Wq, qn_w, qn_b);
    proj_mma<<<2 * NSM, PT, DSM_B>>>(x_k, x_v, kn_w, kn_b);
    attn_kernel<<<B_SZ, 512>>>(Wp, n_w, n_b, out);
}

// round 17
// speedup vs baseline: 1.1476x; 1.0155x over previous
#include <cuda_runtime.h>
#include <cuda_bf16.h>
#include <cuda_fp16.h>
#include <cstdint>

#define B_SZ   1024
#define K_SZ   512
#define D_SZ   256
#define H_SZ   8
#define HD_SZ  32
#define EPS_LN 1e-5f
#define Q_SCALE 0.17677669529663687f   // 32^-0.5

// ---------------- scratch (device globals; allocation-free) ----------------
__device__ float  g_q[B_SZ * D_SZ];                       // 1 MB
__device__ __half g_kh[(size_t)B_SZ * K_SZ * D_SZ];       // 256 MB (LN'd k, fp16)
__device__ __half g_vh[(size_t)B_SZ * K_SZ * D_SZ];       // 256 MB (v, fp16)
__device__ __half g_wh[2][D_SZ * D_SZ];                   // W fp16 (0=Wk,1=Wv)

// ======================= helpers ==============================
__device__ __forceinline__ uint32_t smem_u32(const void* p) {
    uint32_t a;
    asm("{ .reg .u64 t; cvta.to.shared.u64 t, %1; cvt.u32.u64 %0, t; }"
        : "=r"(a) : "l"(p));
    return a;
}
__device__ __forceinline__ uint32_t pack_h2(float a, float b) {
    __half2 t = __floats2half2_rn(a, b);
    return *reinterpret_cast<uint32_t*>(&t);
}

#define LDSM4(r0, r1, r2, r3, addr) \
    asm volatile("ldmatrix.sync.aligned.m8n8.x4.shared.b16 {%0,%1,%2,%3}, [%4];" \
                 : "=r"(r0), "=r"(r1), "=r"(r2), "=r"(r3) : "r"(addr))

#define MMA16816H(c, a, b) \
    asm volatile("mma.sync.aligned.m16n8k16.row.col.f32.f16.f16.f32 " \
                 "{%0,%1,%2,%3}, {%4,%5,%6,%7}, {%8,%9}, {%0,%1,%2,%3};" \
                 : "+f"((c)[0]), "+f"((c)[1]), "+f"((c)[2]), "+f"((c)[3]) \
                 : "r"((a)[0]), "r"((a)[1]), "r"((a)[2]), "r"((a)[3]), \
                   "r"((b)[0]), "r"((b)[1]))

#define CP16(dst, gsrc) \
    asm volatile("cp.async.ca.shared.global [%0], [%1], 16;" \
                 :: "r"(dst), "l"(gsrc) : "memory")
#define CP_COMMIT() asm volatile("cp.async.commit_group;" ::: "memory")
#define CP_WAIT0()  asm volatile("cp.async.wait_group 0;" ::: "memory")

#define GROUP_BAR(id) \
    asm volatile("bar.sync %0, %1;" :: "r"(id), "r"(128) : "memory")

// ============================================================================
// Kernel 0: convert Wk/Wv to fp16.  grid=512, block=256
// ============================================================================
__global__ void wsplit_kernel(const float* __restrict__ Wk,
                              const float* __restrict__ Wv)
{
    const int sel = blockIdx.x & 1;
    const int i   = (blockIdx.x >> 1) * 256 + threadIdx.x;
    g_wh[sel][i] = __float2half_rn((sel ? Wv : Wk)[i]);
}

// ============================================================================
// Kernel 1: q = LN_perhead(x_q @ Wq^T) * scale          grid=B, block=256
// ============================================================================
__global__ void qproj_kernel(const float* __restrict__ xq,
                             const float* __restrict__ Wq,
                             const float* __restrict__ qn_w,
                             const float* __restrict__ qn_b)
{
    const int b = blockIdx.x;
    const int j = threadIdx.x;
    const int lane = j & 31;

    __shared__ float xrow[D_SZ];
    xrow[j] = xq[b * D_SZ + j];
    __syncthreads();

    const float4* w4 = reinterpret_cast<const float4*>(Wq + (size_t)j * D_SZ);
    const float4* x4 = reinterpret_cast<const float4*>(xrow);
    float acc = 0.f;
#pragma unroll
    for (int d = 0; d < D_SZ / 4; ++d) {
        float4 w = w4[d];
        float4 x = x4[d];
        acc = fmaf(w.x, x.x, acc);
        acc = fmaf(w.y, x.y, acc);
        acc = fmaf(w.z, x.z, acc);
        acc = fmaf(w.w, x.w, acc);
    }
    float s = acc, ss = acc * acc;
#pragma unroll
    for (int o = 16; o > 0; o >>= 1) {
        s  += __shfl_xor_sync(0xffffffffu, s,  o);
        ss += __shfl_xor_sync(0xffffffffu, ss, o);
    }
    const float mu  = s * (1.f / 32.f);
    const float var = ss * (1.f / 32.f) - mu * mu;
    const float r   = rsqrtf(var + EPS_LN);
    float q = (acc - mu) * r * qn_w[lane] + qn_b[lane];
    g_q[b * D_SZ + j] = q * Q_SCALE;
}

// ============================================================================
// Kernel 2 (mma.sync fp16, W-resident persistent, GROUP-DECOUPLED):
//   (unchanged from R15 — measured win at 788.8us total)
// ============================================================================
#define CH       64
#define NCH      (D_SZ / CH)      // 4
#define W_OFF    0                 // 4 chunks * 32 KB = 128 KB
#define WCHUNK_B 32768
#define X_OFF    131072            // 4 groups * 2 * 4 KB = 32 KB
#define GBUF_B   4096
#define DSM_B    (X_OFF + 8 * GBUF_B + 1024)
#define PT       512
#define M_TILES  ((B_SZ * K_SZ) / 128)   // 4096
#define NSM      148

__global__ void __launch_bounds__(PT, 1)
proj_mma(const float* __restrict__ x_k, const float* __restrict__ x_v,
         const float* __restrict__ lnw, const float* __restrict__ lnb)
{
    extern __shared__ char dsm[];
    char* smp = (char*)((((uintptr_t)dsm) + 1023) & ~(uintptr_t)1023);
    const uint32_t base = smem_u32(smp);

    const int bid  = blockIdx.x;
    const int wsel = (bid >= NSM) ? 1 : 0;         // 0 = K (LN), 1 = V
    const bool do_ln = (wsel == 0);
    const int tile0 = (bid >= NSM) ? (bid - NSM) : bid;
    const float* __restrict__ X = do_ln ? x_k : x_v;
    const __half* __restrict__ Wh = g_wh[wsel];
    __half* __restrict__ Out = do_ln ? g_kh : g_vh;

    const int tid  = threadIdx.x;
    const int wid  = tid >> 5;
    const int lane = tid & 31;
    const int mh   = wid >> 2;       // 0..3 : group / 32-row stripe
    const int hs   = wid & 3;        // 0..3 : 64-col stripe
    const int g    = lane >> 2;
    const int tg   = lane & 3;
    const int barid = 1 + mh;

    // ---- load W fully into smem (chunked SW128 layout), once ----
#pragma unroll
    for (int i = 0; i < 16; ++i) {
        const int idx = tid + i * PT;           // 0..8191
        const int row = idx >> 5;               // 0..255
        const int rem = idx & 31;
        const int c   = rem >> 3;               // chunk 0..3
        const int j16 = rem & 7;
        const uint32_t off = (uint32_t)c * WCHUNK_B + (uint32_t)row * 128u +
                             (((uint32_t)j16 * 16u) ^ ((uint32_t)(row & 7) * 16u));
        CP16(base + W_OFF + off,
             (const char*)Wh + (size_t)row * 512 + c * 128 + j16 * 16);
    }
    CP_COMMIT();
    CP_WAIT0();
    __syncthreads();        // only whole-CTA sync in the kernel

    // ---- group-local X stage mapping ----
    const int gtid = tid & 127;            // 0..127 within group
    const int grow = gtid >> 2;            // 0..31 : row within group slice
    const int fgrp = gtid & 3;             // 16-float slice of a 64-chunk
    const uint32_t gbase = base + X_OFF + (uint32_t)mh * (2 * GBUF_B);
    const uint32_t xb0   = (uint32_t)fgrp * 32u;
    const uint32_t xswz  = (uint32_t)(grow & 7) * 16u;
    const uint32_t xoff0 = (uint32_t)grow * 128u + (xb0 ^ xswz);
    const uint32_t xoff1 = (uint32_t)grow * 128u + ((xb0 + 16u) ^ xswz);

    float4 xr[4];
    auto stage_x = [&](uint32_t ab) {
        const float* xf = reinterpret_cast<const float*>(xr);
        uint4 h0, h1;
        h0.x = pack_h2(xf[0],  xf[1]);  h0.y = pack_h2(xf[2],  xf[3]);
        h0.z = pack_h2(xf[4],  xf[5]);  h0.w = pack_h2(xf[6],  xf[7]);
        h1.x = pack_h2(xf[8],  xf[9]);  h1.y = pack_h2(xf[10], xf[11]);
        h1.z = pack_h2(xf[12], xf[13]); h1.w = pack_h2(xf[14], xf[15]);
        *reinterpret_cast<uint4*>(smp + (ab - base) + xoff0) = h0;
        *reinterpret_cast<uint4*>(smp + (ab - base) + xoff1) = h1;
    };

    // per-thread global X pointer for the CURRENT tile (row = 32mh + grow)
    const size_t xrow_off = (size_t)(32 * mh + grow) * D_SZ + fgrp * 16;

    // ---- prologue: stage chunk0 of tile0 into group buf0 ----
    {
        const float* xp = X + (size_t)tile0 * 128 * D_SZ + xrow_off;
#pragma unroll
        for (int u = 0; u < 4; ++u)
            xr[u] = *reinterpret_cast<const float4*>(xp + u * 4);
        stage_x(gbase);
    }
    GROUP_BAR(barid);

    // ================= persistent loop over M tiles =================
    for (int tile = tile0; tile < M_TILES; tile += NSM) {
        const size_t m_base = (size_t)tile * 128;
        const float* xptr = X + m_base * D_SZ + xrow_off;

        float acc[2][8][4];
#pragma unroll
        for (int i = 0; i < 2; ++i)
#pragma unroll
            for (int j = 0; j < 8; ++j)
#pragma unroll
                for (int cc = 0; cc < 4; ++cc) acc[i][j][cc] = 0.f;

#pragma unroll
        for (int c = 0; c < NCH; ++c) {
            const int s = c & 1;
            const uint32_t ab = gbase + (uint32_t)s * GBUF_B;
            const uint32_t wb = base + W_OFF + (uint32_t)c * WCHUNK_B;

            // prefetch: next chunk, or chunk0 of the next tile
            const bool have_next = (c + 1 < NCH) || (tile + NSM < M_TILES);
            if (have_next) {
                const float* np = (c + 1 < NCH)
                    ? (xptr + (c + 1) * CH)
                    : (xptr + (size_t)NSM * 128 * D_SZ);
#pragma unroll
                for (int u = 0; u < 4; ++u)
                    xr[u] = *reinterpret_cast<const float4*>(np + u * 4);
            }

            // ---------------- compute chunk c ----------------
#pragma unroll
            for (int ks = 0; ks < 4; ++ks) {
                uint32_t Ah4[2][4], Bh4[8][2];
                {
                    const int ar = lane & 15;
                    const uint32_t akhb = (uint32_t)(lane >> 4) * 16u;
#pragma unroll
                    for (int i = 0; i < 2; ++i) {
                        const int row = 16 * i + ar;      // within group slice
                        const uint32_t off = (uint32_t)row * 128u +
                            (((uint32_t)ks * 32u + akhb) ^ ((uint32_t)(row & 7) * 16u));
                        LDSM4(Ah4[i][0], Ah4[i][1], Ah4[i][2], Ah4[i][3], ab + off);
                    }
                }
                {
                    const int g2  = lane >> 3;
                    const uint32_t khb = (uint32_t)(g2 & 1) * 16u;
                    const int rsub = ((g2 >> 1) * 8) + (lane & 7);
#pragma unroll
                    for (int p = 0; p < 4; ++p) {
                        const int row = hs * 64 + p * 16 + rsub;
                        const uint32_t off = (uint32_t)row * 128u +
                            (((uint32_t)ks * 32u + khb) ^ ((uint32_t)(row & 7) * 16u));
                        LDSM4(Bh4[2 * p][0], Bh4[2 * p][1], Bh4[2 * p + 1][0], Bh4[2 * p + 1][1],
                              wb + off);
                    }
                }
#pragma unroll
                for (int i = 0; i < 2; ++i)
#pragma unroll
                    for (int j = 0; j < 8; ++j)
                        MMA16816H(acc[i][j], Ah4[i], Bh4[j]);
            }

            // stage prefetched data into the other buffer (c=3 -> buf0 of next tile)
            if (have_next)
                stage_x(gbase + (uint32_t)(s ^ 1) * GBUF_B);
            GROUP_BAR(barid);
        }

        // ================= epilogue: per-head LN + fp16 store =================
        float lw[8][2], lb[8][2];
        if (do_ln) {
#pragma unroll
            for (int j = 0; j < 8; ++j) {
                const int c = (j & 3) * 8 + 2 * tg;   // channel-in-head
                lw[j][0] = lnw[c];     lw[j][1] = lnw[c + 1];
                lb[j][0] = lnb[c];     lb[j][1] = lnb[c + 1];
            }
        }

#pragma unroll
        for (int i = 0; i < 2; ++i) {
#pragma unroll
            for (int half = 0; half < 2; ++half) {
                const int r = 32 * mh + 16 * i + 8 * half + g;
                float v0[8], v1[8];
#pragma unroll
                for (int j = 0; j < 8; ++j) {
                    v0[j] = acc[i][j][2 * half];
                    v1[j] = acc[i][j][2 * half + 1];
                }
                if (do_ln) {
#pragma unroll
                    for (int hd = 0; hd < 2; ++hd) {
                        float s = 0.f, ss = 0.f;
#pragma unroll
                        for (int jj = 0; jj < 4; ++jj) {
                            const int j = hd * 4 + jj;
                            s  += v0[j] + v1[j];
                            ss += v0[j] * v0[j] + v1[j] * v1[j];
                        }
                        s  += __shfl_xor_sync(0xffffffffu, s,  1);
                        ss += __shfl_xor_sync(0xffffffffu, ss, 1);
                        s  += __shfl_xor_sync(0xffffffffu, s,  2);
                        ss += __shfl_xor_sync(0xffffffffu, ss, 2);
                        const float mu  = s * (1.f / 32.f);
                        const float var = ss * (1.f / 32.f) - mu * mu;
                        const float rr  = rsqrtf(var + EPS_LN);
#pragma unroll
                        for (int jj = 0; jj < 4; ++jj) {
                            const int j = hd * 4 + jj;
                            v0[j] = (v0[j] - mu) * rr * lw[j][0] + lb[j][0];
                            v1[j] = (v1[j] - mu) * rr * lw[j][1] + lb[j][1];
                        }
                    }
                }
                __half* orow = Out + (m_base + r) * D_SZ + hs * 64 + 2 * tg;
#pragma unroll
                for (int j = 0; j < 8; ++j)
                    *reinterpret_cast<__half2*>(orow + 8 * j) = __floats2half2_rn(v0[j], v1[j]);
            }
        }
    }
}

// ============================================================================
// Kernel 3: attention, cp.async smem streaming. grid=B, block=512, 2 CTAs/SM.
//   16 stages of 32 rows (16 KB k + 16 KB v each), double-buffered in 64 KB
//   dynamic smem. cp.async keeps DRAM busy across barriers (no register cost).
//   Warp w = (head h=w&7, stage-half hf=w>>3); lane (rg=lane>>2, cs=lane&3)
//   reads 16B head-slices from XOR-swizzled smem (conflict-free LDS.128).
// ============================================================================
#define AST_ROWS 32
#define AKBUF    16384                      // 32 rows * 512 B (k)
#define ASTAGE_B 32768                      // k + v
#define ATTN_DSM (2 * ASTAGE_B)             // 64 KB

__global__ void __launch_bounds__(512, 2)
attn_kernel(const float* __restrict__ Wp,
            const float* __restrict__ n_w,
            const float* __restrict__ n_b,
            float* __restrict__ out)
{
    extern __shared__ char abuf[];          // 64 KB dynamic
    const uint32_t abase = smem_u32(abuf);

    const int b    = blockIdx.x;
    const int tid  = threadIdx.x;
    const int w    = tid >> 5;
    const int lane = tid & 31;
    const int h    = w & 7;
    const int hf   = w >> 3;       // 0/1 : which 16-row half of each stage
    const int rg   = lane >> 2;
    const int cs   = lane & 3;

    float qv[8];
    {
        const float4* qp = reinterpret_cast<const float4*>(
            g_q + b * D_SZ + h * HD_SZ + cs * 8);
        float4 a = qp[0], c = qp[1];
        qv[0] = a.x; qv[1] = a.y; qv[2] = a.z; qv[3] = a.w;
        qv[4] = c.x; qv[5] = c.y; qv[6] = c.z; qv[7] = c.w;
    }

    const char* kg = (const char*)(g_kh + (size_t)b * K_SZ * D_SZ);
    const char* vg = (const char*)(g_vh + (size_t)b * K_SZ * D_SZ);

    // stage issue: 4 x CP16 per thread (2 k units + 2 v units)
    auto issue = [&](int s) {
        const uint32_t bb = abase + (uint32_t)(s & 1) * ASTAGE_B;
        const char* ks = kg + (size_t)s * AST_ROWS * 512;
        const char* vs = vg + (size_t)s * AST_ROWS * 512;
#pragma unroll
        for (int i = 0; i < 2; ++i) {
            const int u   = tid + i * 512;
            const int row = u >> 5;
            const int j   = u & 31;
            const uint32_t doff = (uint32_t)row * 512u +
                                  (uint32_t)((j ^ ((row & 7) << 2)) << 4);
            CP16(bb + doff,         ks + (size_t)row * 512 + j * 16);
            CP16(bb + AKBUF + doff, vs + (size_t)row * 512 + j * 16);
        }
    };

    // reader offsets (two rows per lane per stage)
    const int r0l = hf * 16 + rg;
    const int r1l = r0l + 8;
    const uint32_t ju = (uint32_t)(h * 4 + cs);
    const uint32_t o0 = (uint32_t)r0l * 512u + ((ju ^ ((uint32_t)(r0l & 7) << 2)) << 4);
    const uint32_t o1 = (uint32_t)r1l * 512u + ((ju ^ ((uint32_t)(r1l & 7) << 2)) << 4);

    float m = -1e30f, l = 0.f;
    float acc[8];
#pragma unroll
    for (int e = 0; e < 8; ++e) acc[e] = 0.f;

    issue(0); CP_COMMIT();

#pragma unroll 1
    for (int s = 0; s < 16; ++s) {
        if (s + 1 < 16) {
            issue(s + 1); CP_COMMIT();
            asm volatile("cp.async.wait_group 1;" ::: "memory");
        } else {
            asm volatile("cp.async.wait_group 0;" ::: "memory");
        }
        __syncthreads();

        const char* bb = abuf + (s & 1) * ASTAGE_B;
        const uint4 k0 = *reinterpret_cast<const uint4*>(bb + o0);
        const uint4 k1 = *reinterpret_cast<const uint4*>(bb + o1);
        const uint4 v0 = *reinterpret_cast<const uint4*>(bb + AKBUF + o0);
        const uint4 v1 = *reinterpret_cast<const uint4*>(bb + AKBUF + o1);

        float s0 = 0.f, s1 = 0.f;
        {
            const __half2* kh0 = reinterpret_cast<const __half2*>(&k0);
            const __half2* kh1 = reinterpret_cast<const __half2*>(&k1);
#pragma unroll
            for (int e = 0; e < 4; ++e) {
                const float2 f0 = __half22float2(kh0[e]);
                const float2 f1 = __half22float2(kh1[e]);
                s0 = fmaf(qv[2 * e], f0.x, s0); s0 = fmaf(qv[2 * e + 1], f0.y, s0);
                s1 = fmaf(qv[2 * e], f1.x, s1); s1 = fmaf(qv[2 * e + 1], f1.y, s1);
            }
            s0 += __shfl_xor_sync(0xffffffffu, s0, 1);
            s0 += __shfl_xor_sync(0xffffffffu, s0, 2);
            s1 += __shfl_xor_sync(0xffffffffu, s1, 1);
            s1 += __shfl_xor_sync(0xffffffffu, s1, 2);
        }

        const float mn   = fmaxf(m, fmaxf(s0, s1));
        const float corr = __expf(m - mn);
        const float p0   = __expf(s0 - mn);
        const float p1   = __expf(s1 - mn);
        l = l * corr + p0 + p1;
        {
            const __half2* vh0 = reinterpret_cast<const __half2*>(&v0);
            const __half2* vh1 = reinterpret_cast<const __half2*>(&v1);
#pragma unroll
            for (int e = 0; e < 4; ++e) {
                const float2 f0 = __half22float2(vh0[e]);
                const float2 f1 = __half22float2(vh1[e]);
                acc[2 * e]     = fmaf(acc[2 * e],     corr, p0 * f0.x + p1 * f1.x);
                acc[2 * e + 1] = fmaf(acc[2 * e + 1], corr, p0 * f0.y + p1 * f1.y);
            }
        }
        m = mn;
        __syncthreads();
    }

    // ---- intra-warp merge over 8 row-groups (lanes xor 4,8,16) ----
#pragma unroll
    for (int off = 4; off <= 16; off <<= 1) {
        const float pm = __shfl_xor_sync(0xffffffffu, m, off);
        const float pl = __shfl_xor_sync(0xffffffffu, l, off);
        const float MM = fmaxf(m, pm);
        const float ca = __expf(m - MM);
        const float cb = __expf(pm - MM);
        l = l * ca + pl * cb;
#pragma unroll
        for (int e = 0; e < 8; ++e) {
            const float pa = __shfl_xor_sync(0xffffffffu, acc[e], off);
            acc[e] = acc[e] * ca + pa * cb;
        }
        m = MM;
    }

    // ---- cross-warp merge (w and w+8 share a head) ----
    __shared__ float sm[16], sl[16];
    __shared__ float sacc[16][33];
    if (lane == 0) { sm[w] = m; sl[w] = l; }
    if (rg == 0) {
#pragma unroll
        for (int e = 0; e < 8; ++e) sacc[w][cs * 8 + e] = acc[e];
    }
    __syncthreads();

    float o_val = 0.f;
    if (tid < 256) {
        const int hh = tid >> 5;       // head
        const int ch = tid & 31;       // channel within head
        const float m0 = sm[hh], m1 = sm[hh + 8];
        const float M  = fmaxf(m0, m1);
        const float c0 = __expf(m0 - M), c1 = __expf(m1 - M);
        const float L  = sl[hh] * c0 + sl[hh + 8] * c1;
        o_val = (sacc[hh][ch] * c0 + sacc[hh + 8][ch] * c1) / L;
    }

    // ---- block LN over 256 channels (threads 0..255 hold o_val) ----
    __shared__ float sred[2][8];
    if (tid < 256) {
        float s = o_val, ss = o_val * o_val;
#pragma unroll
        for (int off = 16; off > 0; off >>= 1) {
            s  += __shfl_xor_sync(0xffffffffu, s,  off);
            ss += __shfl_xor_sync(0xffffffffu, ss, off);
        }
        if (lane == 0) { sred[0][w] = s; sred[1][w] = ss; }
    }
    __syncthreads();
    float ts = 0.f, tss = 0.f;
#pragma unroll
    for (int i = 0; i < 8; ++i) { ts += sred[0][i]; tss += sred[1][i]; }
    const float mu  = ts * (1.f / 256.f);
    const float var = tss * (1.f / 256.f) - mu * mu;
    const float rln = rsqrtf(var + EPS_LN);

    __shared__ float sn[D_SZ];
    if (tid < 256)
        sn[tid] = (o_val - mu) * rln * n_w[tid] + n_b[tid];
    __syncthreads();

    // ---- out @ Wp^T : 2 threads per output column (split K 128+128) ----
    const int c   = tid & 255;
    const int seg = tid >> 8;
    const float4* w4 = reinterpret_cast<const float4*>(Wp + (size_t)c * D_SZ + seg * 128);
    const float4* x4 = reinterpret_cast<const float4*>(sn + seg * 128);
    float a = 0.f;
#pragma unroll
    for (int d = 0; d < 32; ++d) {
        float4 wv = w4[d];
        float4 xv = x4[d];
        a = fmaf(wv.x, xv.x, a);
        a = fmaf(wv.y, xv.y, a);
        a = fmaf(wv.z, xv.z, a);
        a = fmaf(wv.w, xv.w, a);
    }
    __shared__ float part[256];
    if (seg == 1) part[c] = a;
    __syncthreads();
    if (seg == 0) out[b * D_SZ + c] = a + part[c];
}

// ============================================================================
extern "C" void kernel_launch(void* const* d_in, const int* in_sizes, int n_in,
                              void* d_out, int out_size)
{
    const float* x_q  = (const float*)d_in[0];
    const float* x_k  = (const float*)d_in[1];
    const float* x_v  = (const float*)d_in[2];
    const float* Wq   = (const float*)d_in[3];
    const float* Wk   = (const float*)d_in[4];
    const float* Wv   = (const float*)d_in[5];
    const float* Wp   = (const float*)d_in[6];
    const float* qn_w = (const float*)d_in[7];
    const float* qn_b = (const float*)d_in[8];
    const float* kn_w = (const float*)d_in[9];
    const float* kn_b = (const float*)d_in[10];
    const float* n_w  = (const float*)d_in[11];
    const float* n_b  = (const float*)d_in[12];
    float* out = (float*)d_out;

    cudaFuncSetAttribute(proj_mma,
                         cudaFuncAttributeMaxDynamicSharedMemorySize, DSM_B);
    cudaFuncSetAttribute(attn_kernel,
                         cudaFuncAttributeMaxDynamicSharedMemorySize, ATTN_DSM);

    wsplit_kernel<<<512, 256>>>(Wk, Wv);
    qproj_kernel<<<B_SZ, 256>>>(x_q, Wq, qn_w, qn_b);
    proj_mma<<<2 * NSM, PT, DSM_B>>>(x_k, x_v, kn_w, kn_b);
    attn_kernel<<<B_SZ, 512, ATTN_DSM>>>(Wp, n_w, n_b, out);
}